// round 4
// baseline (speedup 1.0000x reference)
#include <cuda_runtime.h>
#include <cstdint>

// Problem constants
#define NB   8
#define TPD  2048
#define ED   4096
#define TD   16384
#define VD   17
#define OUTROWS 131072
#define KS   8           // K-splits
#define KCHUNK 512       // ED/KS
#define QCHUNK 128       // KCHUNK/4 (float4 quads)
#define RMAX 16384       // hard upper bound on per-batch masked count

typedef unsigned long long ull;

// Scratch (device globals)
__device__ float g_WeffQ[8 * 1024 * 32];      // [s0][q][32] quad-interleaved Weff, 4MB
__device__ float g_beff[8];
__device__ int   g_bucket[64 * 2048];         // [(n*8+s0)][slot] = (r<<16)|tp
__device__ int   g_bcount[64];
__device__ int   g_count8[NB];                // 8 * per-batch masked count
__device__ float g_part[(size_t)KS * NB * RMAX * 8];  // [ks][n][r][s], 33.5MB

// ---------------------------------------------------------------------------
__device__ __forceinline__ void ffma2(ull& d, ull a, ull b) {
    asm("fma.rn.f32x2 %0, %1, %2, %0;" : "+l"(d) : "l"(a), "l"(b));
}
__device__ __forceinline__ void ldgsts16(void* dst, const void* src) {
    unsigned saddr = (unsigned)__cvta_generic_to_shared(dst);
    asm volatile("cp.async.cg.shared.global [%0], [%1], 16;\n" :: "r"(saddr), "l"(src));
}
__device__ __forceinline__ void cp_commit() {
    asm volatile("cp.async.commit_group;\n" ::: "memory");
}
template <int N>
__device__ __forceinline__ void cp_wait() {
    asm volatile("cp.async.wait_group %0;\n" :: "n"(N) : "memory");
}

// ---------------------------------------------------------------------------
// K01 fused: blocks [0,512) build WeffQ (+beff at block 0); blocks [512,520)
// do per-batch argmax + bucketed stream compaction. 512 threads.
// ---------------------------------------------------------------------------
__global__ __launch_bounds__(512) void k01(const float* __restrict__ W1,
                                           const float* __restrict__ W2,
                                           const float* __restrict__ b1,
                                           const float* __restrict__ b2,
                                           const int* __restrict__ value,
                                           const int* __restrict__ depth) {
    int bid = blockIdx.x;
    int tid = threadIdx.x;
    __shared__ float w2s[512];
    __shared__ float w1r[8][512];
    __shared__ int wsum[16];
    __shared__ int s_idx;

    if (bid < 512) {
        // ---- Weff: 8 e-values per block ----
        int e0 = bid * 8;
        w2s[tid] = W2[tid];
        for (int i = tid; i < 4096; i += 512) w1r[i >> 9][i & 511] = W1[e0 * 512 + i];
        __syncthreads();
        int sub = tid >> 6;       // which e (0..7)
        int t64 = tid & 63;
        int s0 = t64 >> 3, s = t64 & 7;
        int e = e0 + sub;
        float acc = 0.f;
#pragma unroll
        for (int c = 0; c < 64; c++) acc += w1r[sub][c * 8 + s0] * w2s[c * 8 + s];
        int q = e >> 2, p = (e >> 1) & 1, h = e & 1;
        g_WeffQ[(s0 * 1024 + q) * 32 + p * 16 + s * 2 + h] = acc;
        if (bid == 0 && tid < 8) {
            float a = 0.f;
#pragma unroll
            for (int c = 0; c < 64; c++) a += b1[c] * w2s[c * 8 + tid];
            g_beff[tid] = a + b2[0];
        }
    } else {
        // ---- prep: batch n ----
        int n = bid - 512;
        const int* dep = depth + n * TD;
        const int* val = value + n * TD;
        if (tid < 8) g_bcount[n * 8 + tid] = 0;
        int maxv = dep[TD - 1];
        if (tid == 0) s_idx = TD;
        __syncthreads();
        for (int t = tid; t < TD; t += 512) {
            if (dep[t] == maxv && (t == 0 || dep[t - 1] < maxv)) atomicMin(&s_idx, t);
        }
        __syncthreads();
        int idx = s_idx;

        int base = tid * 32;
        unsigned mb = 0;
        int cnt = 0;
#pragma unroll
        for (int j = 0; j < 32; j++) {
            int t = base + j;
            bool m = (t < idx) && (val[t] == 2);
            mb |= ((unsigned)m) << j;
            cnt += (int)m;
        }
        int lane = tid & 31, wid = tid >> 5;
        int v = cnt;
#pragma unroll
        for (int o = 1; o < 32; o <<= 1) {
            int u = __shfl_up_sync(0xffffffffu, v, o);
            if (lane >= o) v += u;
        }
        if (lane == 31) wsum[wid] = v;
        __syncthreads();
        if (tid < 32) {
            int w = (tid < 16) ? wsum[tid] : 0;
#pragma unroll
            for (int o = 1; o < 16; o <<= 1) {
                int u = __shfl_up_sync(0xffffffffu, w, o);
                if (lane >= o) w += u;
            }
            if (tid < 16) wsum[tid] = w;
        }
        __syncthreads();
        int warpbase = (wid == 0) ? 0 : wsum[wid - 1];
        int r = warpbase + v - cnt;

        for (int j = 0; j < 32; j++) {
            if ((mb >> j) & 1u) {
                int t = base + j;
                int s0 = t & 7, tp = t >> 3;
                int slot = atomicAdd(&g_bcount[n * 8 + s0], 1);
                g_bucket[(n * 8 + s0) * 2048 + slot] = (r << 16) | tp;
                r++;
            }
        }
        __syncthreads();
        if (tid == 0) {
            int ssum = 0;
#pragma unroll
            for (int i = 0; i < 8; i++) ssum += g_bcount[n * 8 + i];
            g_count8[n] = 8 * ssum;
        }
    }
}

// ---------------------------------------------------------------------------
// K3: row-per-thread GEMM. Block = 128 threads, RM=2 -> 256 rows/block.
// Each thread owns 2 whole rows (all 8 s), K chunk of 512 (ks split).
// X: global->reg prefetch (LDG.128), W: tiny smem broadcast, f32x2 FMA.
// Partials -> g_part[ks][n][r][s].
// blockIdx.x = rb*64 + ks*8 + s0 (s0 fastest for L2 reuse across buckets)
// ---------------------------------------------------------------------------
__global__ __launch_bounds__(128) void k3_heavy(const float* __restrict__ x) {
    int bx = blockIdx.x;
    int s0 = bx & 7, ks = (bx >> 3) & 7, rb = bx >> 6;
    int n = blockIdx.y;
    int bucket = n * 8 + s0;
    int bcnt = g_bcount[bucket];
    int row0 = rb * 256;
    if (row0 >= bcnt) return;
    int tid = threadIdx.x;

    __shared__ __align__(16) float Wq[QCHUNK][32];  // 16KB

    const float* wsrc = g_WeffQ + (size_t)(s0 * 1024 + ks * QCHUNK) * 32;
#pragma unroll
    for (int i = 0; i < 8; i++) {
        int f = i * 128 + tid;
        ldgsts16(&Wq[0][0] + f * 4, wsrc + f * 4);
    }
    cp_commit();

    int grA = row0 + tid, grB = row0 + 128 + tid;
    bool vA = grA < bcnt, vB = grB < bcnt;
    int pA = vA ? g_bucket[bucket * 2048 + grA] : 0;
    int pB = vB ? g_bucket[bucket * 2048 + grB] : 0;
    int rA = pA >> 16, tpA = pA & 0xFFFF;
    int rB = pB >> 16, tpB = pB & 0xFFFF;

    const ulonglong2* xA = (const ulonglong2*)(x + ((size_t)n * TPD + tpA) * ED + ks * KCHUNK);
    const ulonglong2* xB = (const ulonglong2*)(x + ((size_t)n * TPD + tpB) * ED + ks * KCHUNK);

    ull accA[8], accB[8];
#pragma unroll
    for (int s = 0; s < 8; s++) { accA[s] = 0ull; accB[s] = 0ull; }

    ulonglong2 bufA[2], bufB[2];
    bufA[0] = xA[0];
    bufB[0] = xB[0];

    cp_wait<0>();
    __syncthreads();

#pragma unroll 2
    for (int q = 0; q < QCHUNK; q++) {
        int cur = q & 1;
        if (q + 1 < QCHUNK) {
            bufA[cur ^ 1] = xA[q + 1];
            bufB[cur ^ 1] = xB[q + 1];
        }
        ulonglong2 xa = bufA[cur];
        ulonglong2 xb = bufB[cur];
#pragma unroll
        for (int m = 0; m < 8; m++) {
            ulonglong2 wv = *(const ulonglong2*)&Wq[q][m * 4];
            ull xpa = (m < 4) ? xa.x : xa.y;
            ull xpb = (m < 4) ? xb.x : xb.y;
            int s2 = (m & 3) * 2;
            ffma2(accA[s2],     xpa, wv.x);
            ffma2(accA[s2 + 1], xpa, wv.y);
            ffma2(accB[s2],     xpb, wv.x);
            ffma2(accB[s2 + 1], xpb, wv.y);
        }
    }

    // horizontal add of f32x2 halves, store partials
    float ya[8], yb[8];
#pragma unroll
    for (int s = 0; s < 8; s++) {
        float2 fa = *(float2*)&accA[s];
        float2 fb = *(float2*)&accB[s];
        ya[s] = fa.x + fa.y;
        yb[s] = fb.x + fb.y;
    }
    if (vA) {
        float* dst = g_part + ((size_t)(ks * NB + n) * RMAX + rA) * 8;
        *(float4*)(dst)     = make_float4(ya[0], ya[1], ya[2], ya[3]);
        *(float4*)(dst + 4) = make_float4(ya[4], ya[5], ya[6], ya[7]);
    }
    if (vB) {
        float* dst = g_part + ((size_t)(ks * NB + n) * RMAX + rB) * 8;
        *(float4*)(dst)     = make_float4(yb[0], yb[1], yb[2], yb[3]);
        *(float4*)(dst + 4) = make_float4(yb[4], yb[5], yb[6], yb[7]);
    }
}

// ---------------------------------------------------------------------------
// K4: fused epilogue + default fill. Strip of 256 output rows per block.
// Heavy rows (j < 8*count): y2 = sum_ks part + beff[s]; tail: y2 = b2.
// out[n,j,v] = y2*W3[v], written coalesced via smem-staged y2.
// ---------------------------------------------------------------------------
__global__ __launch_bounds__(256) void k4_epi(const float* __restrict__ W3,
                                              const float* __restrict__ b2,
                                              float* __restrict__ out) {
    int n = blockIdx.y;
    int j0 = blockIdx.x * 256;
    int tid = threadIdx.x;
    __shared__ float y2s[256];
    __shared__ float w3s[VD];
    __shared__ float beffs[8];
    if (tid < VD) w3s[tid] = W3[tid];
    if (tid < 8) beffs[tid] = g_beff[tid];
    __syncthreads();

    int count8 = g_count8[n];
    int j = j0 + tid;
    float acc;
    if (j < count8) {
        acc = beffs[j & 7];
#pragma unroll
        for (int ksi = 0; ksi < KS; ksi++)
            acc += g_part[(size_t)(ksi * NB + n) * (RMAX * 8) + j];
    } else {
        acc = b2[0];
    }
    y2s[tid] = acc;
    __syncthreads();

    float* ob = out + ((size_t)n * OUTROWS + j0) * VD;
    const int NF4 = 256 * VD / 4;  // 1088
    for (int f = tid; f < NF4; f += 256) {
        float4 o;
#pragma unroll
        for (int c = 0; c < 4; c++) {
            int idx = f * 4 + c;
            int jj = idx / VD;
            int vv = idx - jj * VD;
            ((float*)&o)[c] = y2s[jj] * w3s[vv];
        }
        *(float4*)(ob + f * 4) = o;
    }
}

// ---------------------------------------------------------------------------
extern "C" void kernel_launch(void* const* d_in, const int* in_sizes, int n_in,
                              void* d_out, int out_size) {
    const float* x     = (const float*)d_in[0];
    const int*   value = (const int*)d_in[1];   // jax x64-off: int32
    const int*   depth = (const int*)d_in[2];
    // d_in[3] = pos, unused
    const float* W1    = (const float*)d_in[4];
    const float* b1    = (const float*)d_in[5];
    const float* W2    = (const float*)d_in[6];
    const float* b2    = (const float*)d_in[7];
    const float* W3    = (const float*)d_in[8];
    float* out = (float*)d_out;

    k01<<<520, 512>>>(W1, W2, b1, b2, value, depth);
    k3_heavy<<<dim3(512, NB), 128>>>(x);
    k4_epi<<<dim3(OUTROWS / 256, NB), 256>>>(W3, b2, out);
}

// round 5
// speedup vs baseline: 1.9513x; 1.9513x over previous
#include <cuda_runtime.h>
#include <cstdint>

// Problem constants
#define NB   8
#define TPD  2048
#define ED   4096
#define TD   16384
#define VD   17
#define OUTROWS 131072
#define KS   8           // K-splits
#define KCHUNK 512       // ED/KS
#define KT   16          // K per pipeline stage
#define NSTAGE (KCHUNK/KT)  // 32
#define MROWS 256        // rows per k3 block
#define RMAX 16384       // hard upper bound on per-batch masked count

typedef unsigned long long ull;

// Scratch (device globals)
__device__ float g_WeffQ[8 * 1024 * 32];      // [s0][q][32] quad-interleaved Weff
__device__ float g_beff[8];
__device__ int   g_bucket[64 * 2048];         // [(n*8+s0)][slot] = (r<<16)|tp
__device__ int   g_bcount[64];
__device__ int   g_count8[NB];                // 8 * per-batch masked count
__device__ float g_part[(size_t)KS * NB * RMAX * 8];  // [ks][n][r][s]

// ---------------------------------------------------------------------------
__device__ __forceinline__ void ffma2(ull& d, ull a, ull b) {
    asm("fma.rn.f32x2 %0, %1, %2, %0;" : "+l"(d) : "l"(a), "l"(b));
}
__device__ __forceinline__ void ldgsts16(void* dst, const void* src) {
    unsigned saddr = (unsigned)__cvta_generic_to_shared(dst);
    asm volatile("cp.async.cg.shared.global [%0], [%1], 16;\n" :: "r"(saddr), "l"(src));
}
__device__ __forceinline__ void cp_commit() {
    asm volatile("cp.async.commit_group;\n" ::: "memory");
}
template <int N>
__device__ __forceinline__ void cp_wait() {
    asm volatile("cp.async.wait_group %0;\n" :: "n"(N) : "memory");
}

// ---------------------------------------------------------------------------
// K01 fused: blocks [0,512) build WeffQ (+beff at block 0); blocks [512,520)
// do per-batch argmax + bucketed stream compaction (atomic-free slot calc).
// ---------------------------------------------------------------------------
__global__ __launch_bounds__(512) void k01(const float* __restrict__ W1,
                                           const float* __restrict__ W2,
                                           const float* __restrict__ b1,
                                           const float* __restrict__ b2,
                                           const int* __restrict__ value,
                                           const int* __restrict__ depth) {
    int bid = blockIdx.x;
    int tid = threadIdx.x;

    if (bid < 512) {
        // ---- Weff: 8 e-values per block ----
        __shared__ float w2s[512];
        __shared__ float w1r[8][512];
        int e0 = bid * 8;
        w2s[tid] = W2[tid];
        for (int i = tid; i < 4096; i += 512) w1r[i >> 9][i & 511] = W1[e0 * 512 + i];
        __syncthreads();
        int sub = tid >> 6;       // which e (0..7)
        int t64 = tid & 63;
        int s0 = t64 >> 3, s = t64 & 7;
        int e = e0 + sub;
        float acc = 0.f;
#pragma unroll
        for (int c = 0; c < 64; c++) acc += w1r[sub][c * 8 + s0] * w2s[c * 8 + s];
        int q = e >> 2, p = (e >> 1) & 1, h = e & 1;
        g_WeffQ[(s0 * 1024 + q) * 32 + p * 16 + s * 2 + h] = acc;
        if (bid == 0 && tid < 8) {
            float a = 0.f;
#pragma unroll
            for (int c = 0; c < 64; c++) a += b1[c] * w2s[c * 8 + tid];
            g_beff[tid] = a + b2[0];
        }
    } else {
        // ---- prep: batch n, no global atomics ----
        int n = bid - 512;
        const int* dep = depth + n * TD;
        const int* val = value + n * TD;
        __shared__ int s_idx;
        __shared__ int wsum[16];
        __shared__ ull wtot8[16];
        __shared__ int wbase[16 * 8];

        int maxv = dep[TD - 1];
        if (tid == 0) s_idx = TD;
        __syncthreads();
        for (int t = tid; t < TD; t += 512) {
            if (dep[t] == maxv && (t == 0 || dep[t - 1] < maxv)) atomicMin(&s_idx, t);
        }
        __syncthreads();
        int idx = s_idx;

        int base = tid * 32;
        unsigned mb = 0;
        int cnt = 0;
        ull c8 = 0;   // packed per-s0 counts, 8x8 bits (each <= 4)
#pragma unroll
        for (int j = 0; j < 32; j++) {
            int t = base + j;
            bool m = (t < idx) && (val[t] == 2);
            mb |= ((unsigned)m) << j;
            cnt += (int)m;
            if (m) c8 += 1ull << ((j & 7) * 8);
        }
        int lane = tid & 31, wid = tid >> 5;
        // warp inclusive scans: scalar rank + packed per-s0
        int v = cnt;
        ull ci = c8;
#pragma unroll
        for (int o = 1; o < 32; o <<= 1) {
            int u = __shfl_up_sync(0xffffffffu, v, o);
            ull u8 = __shfl_up_sync(0xffffffffu, ci, o);
            if (lane >= o) { v += u; ci += u8; }
        }
        if (lane == 31) { wsum[wid] = v; wtot8[wid] = ci; }
        __syncthreads();
        if (tid < 32) {
            int w = (tid < 16) ? wsum[tid] : 0;
#pragma unroll
            for (int o = 1; o < 16; o <<= 1) {
                int u = __shfl_up_sync(0xffffffffu, w, o);
                if (lane >= o) w += u;
            }
            if (tid < 16) wsum[tid] = w;
        } else if (tid < 40) {
            int s0 = tid - 32;
            int run = 0;
#pragma unroll
            for (int w = 0; w < 16; w++) {
                int c = (int)((wtot8[w] >> (s0 * 8)) & 0xFF);
                wbase[w * 8 + s0] = run;
                run += c;
            }
            g_bcount[n * 8 + s0] = run;
        }
        __syncthreads();
        int warpbase = (wid == 0) ? 0 : wsum[wid - 1];
        int r = warpbase + v - cnt;
        ull excl = ci - c8;
        int slot[8];
#pragma unroll
        for (int s0 = 0; s0 < 8; s0++)
            slot[s0] = wbase[wid * 8 + s0] + (int)((excl >> (s0 * 8)) & 0xFF);
        int bb = n * 8;
#pragma unroll
        for (int j = 0; j < 32; j++) {
            if ((mb >> j) & 1u) {
                int t = base + j;
                int s0 = j & 7;
                g_bucket[(bb + s0) * 2048 + slot[s0]] = (r << 16) | (t >> 3);
                slot[s0]++;
                r++;
            }
        }
        if (tid == 0) {
            int ss = 0;
#pragma unroll
            for (int i = 0; i < 8; i++) ss += g_bcount[bb + i];
            g_count8[n] = 8 * ss;
        }
    }
}

// ---------------------------------------------------------------------------
// K3: bucketed GEMM. 64 threads/block, 256 rows/block, thread owns 4 rows
// (tid, tid+64, tid+128, tid+192) x all 8 s. X staged via cp.async into smem
// with 20-float row stride (conflict-free), W warp-broadcast, f32x2 FMA.
// K split by ks into 512-float chunks; 32 double-buffered stages of KT=16.
// blockIdx.x = rb*64 + ks*8 + s0 (s0 fastest for L2 reuse across buckets).
// ---------------------------------------------------------------------------
#define XSTRIDE 20

__global__ __launch_bounds__(64) void k3_heavy(const float* __restrict__ x) {
    int bx = blockIdx.x;
    int s0 = bx & 7, ks = (bx >> 3) & 7, rb = bx >> 6;
    int n = blockIdx.y;
    int bucket = n * 8 + s0;
    int bcnt = g_bcount[bucket];
    int row0 = rb * MROWS;
    if (row0 >= bcnt) return;
    int tid = threadIdx.x;

    __shared__ __align__(16) float Xs[2][MROWS][XSTRIDE];  // 40KB
    __shared__ __align__(16) float Wsm[2][4][32];          // 1KB
    __shared__ int stp_s[MROWS];
    __shared__ int sr_s[MROWS];

    // prologue: row metadata (coalesced)
#pragma unroll
    for (int i = 0; i < 4; i++) {
        int li = tid + 64 * i;
        int gr = row0 + li;
        if (gr < bcnt) {
            int p = g_bucket[bucket * 2048 + gr];
            sr_s[li] = p >> 16;
            stp_s[li] = p & 0xFFFF;
        } else {
            sr_s[li] = -1;
            stp_s[li] = 0;
        }
    }
    __syncthreads();

    const float* xb = x + (size_t)n * TPD * ED + ks * KCHUNK;
    const float* wb = g_WeffQ + (size_t)(s0 * 1024 + ks * 128) * 32;

    // loader mapping: gidx = i*64+tid; row = gidx>>2, q = gidx&3
    // lanes 0-3 cover one row's 4 quads (64B contiguous global).
    auto load_stage = [&](int st, int b) {
        int kbase = st * KT;
#pragma unroll
        for (int i = 0; i < 16; i++) {
            int gidx = i * 64 + tid;
            int row = gidx >> 2, q = gidx & 3;
            ldgsts16(&Xs[b][row][q * 4],
                     xb + (size_t)stp_s[row] * ED + kbase + q * 4);
        }
        if (tid < 32) {
            ldgsts16(&Wsm[b][0][tid * 4], wb + st * 128 + tid * 4);
        }
        cp_commit();
    };

    load_stage(0, 0);

    ull acc[4][8];
#pragma unroll
    for (int i = 0; i < 4; i++)
#pragma unroll
        for (int s = 0; s < 8; s++) acc[i][s] = 0ull;

    for (int st = 0; st < NSTAGE; st++) {
        int b = st & 1;
        if (st + 1 < NSTAGE) {
            load_stage(st + 1, b ^ 1);
            cp_wait<1>();
        } else {
            cp_wait<0>();
        }
        __syncthreads();

#pragma unroll
        for (int q = 0; q < 4; q++) {
            ulonglong2 xq[4];
#pragma unroll
            for (int i = 0; i < 4; i++)
                xq[i] = *(const ulonglong2*)&Xs[b][tid + 64 * i][q * 4];
            const ull* wq = (const ull*)&Wsm[b][q][0];
#pragma unroll
            for (int sp = 0; sp < 4; sp++) {
                ulonglong2 w0 = *(const ulonglong2*)(wq + sp * 2);      // p=0: s=2sp,2sp+1
                ulonglong2 w1 = *(const ulonglong2*)(wq + 8 + sp * 2);  // p=1
#pragma unroll
                for (int i = 0; i < 4; i++) {
                    ffma2(acc[i][2 * sp],     xq[i].x, w0.x);
                    ffma2(acc[i][2 * sp],     xq[i].y, w1.x);
                    ffma2(acc[i][2 * sp + 1], xq[i].x, w0.y);
                    ffma2(acc[i][2 * sp + 1], xq[i].y, w1.y);
                }
            }
        }
        __syncthreads();
    }

    // store partials
#pragma unroll
    for (int i = 0; i < 4; i++) {
        int li = tid + 64 * i;
        int rr = sr_s[li];
        if (rr < 0) continue;
        float y[8];
#pragma unroll
        for (int s = 0; s < 8; s++) {
            float2 f = *(float2*)&acc[i][s];
            y[s] = f.x + f.y;
        }
        float* dst = g_part + ((size_t)(ks * NB + n) * RMAX + rr) * 8;
        *(float4*)(dst)     = make_float4(y[0], y[1], y[2], y[3]);
        *(float4*)(dst + 4) = make_float4(y[4], y[5], y[6], y[7]);
    }
}

// ---------------------------------------------------------------------------
// K4: fused epilogue + default fill. Strip of 256 output rows per block.
// ---------------------------------------------------------------------------
__global__ __launch_bounds__(256) void k4_epi(const float* __restrict__ W3,
                                              const float* __restrict__ b2,
                                              float* __restrict__ out) {
    int n = blockIdx.y;
    int j0 = blockIdx.x * 256;
    int tid = threadIdx.x;
    __shared__ float y2s[256];
    __shared__ float w3s[VD];
    __shared__ float beffs[8];
    if (tid < VD) w3s[tid] = W3[tid];
    if (tid < 8) beffs[tid] = g_beff[tid];
    __syncthreads();

    int count8 = g_count8[n];
    int j = j0 + tid;
    float acc;
    if (j < count8) {
        acc = beffs[j & 7];
#pragma unroll
        for (int ksi = 0; ksi < KS; ksi++)
            acc += g_part[(size_t)(ksi * NB + n) * (RMAX * 8) + j];
    } else {
        acc = b2[0];
    }
    y2s[tid] = acc;
    __syncthreads();

    float* ob = out + ((size_t)n * OUTROWS + j0) * VD;
    const int NF4 = 256 * VD / 4;  // 1088
    for (int f = tid; f < NF4; f += 256) {
        float4 o;
#pragma unroll
        for (int c = 0; c < 4; c++) {
            int idx = f * 4 + c;
            int jj = idx / VD;
            int vv = idx - jj * VD;
            ((float*)&o)[c] = y2s[jj] * w3s[vv];
        }
        *(float4*)(ob + f * 4) = o;
    }
}

// ---------------------------------------------------------------------------
extern "C" void kernel_launch(void* const* d_in, const int* in_sizes, int n_in,
                              void* d_out, int out_size) {
    const float* x     = (const float*)d_in[0];
    const int*   value = (const int*)d_in[1];   // jax x64-off: int32
    const int*   depth = (const int*)d_in[2];
    // d_in[3] = pos, unused
    const float* W1    = (const float*)d_in[4];
    const float* b1    = (const float*)d_in[5];
    const float* W2    = (const float*)d_in[6];
    const float* b2    = (const float*)d_in[7];
    const float* W3    = (const float*)d_in[8];
    float* out = (float*)d_out;

    k01<<<520, 512>>>(W1, W2, b1, b2, value, depth);
    k3_heavy<<<dim3(512, NB), 64>>>(x);
    k4_epi<<<dim3(OUTROWS / 256, NB), 256>>>(W3, b2, out);
}

// round 6
// speedup vs baseline: 1.9561x; 1.0025x over previous
#include <cuda_runtime.h>
#include <cstdint>

// Problem constants
#define NB   8
#define TPD  2048
#define ED   4096
#define TD   16384
#define VD   17
#define OUTROWS 131072
#define KS   8           // K-splits
#define KCHUNK 512       // ED/KS
#define KT   16          // K per pipeline stage
#define NSTAGE (KCHUNK/KT)  // 32
#define MROWS 256        // rows per k3 block
#define RMAX 16384       // hard upper bound on per-batch masked count

typedef unsigned long long ull;

// Scratch (device globals)
__device__ float g_WeffQ[8 * 1024 * 32];      // [s0][q][32] quad-interleaved Weff
__device__ float g_beff[8];
__device__ int   g_bucket[64 * 2048];         // [(n*8+s0)][slot] = (r<<16)|tp
__device__ int   g_bcount[64];
__device__ int   g_count8[NB];                // 8 * per-batch masked count
__device__ float g_part[(size_t)KS * NB * RMAX * 8];  // [ks][n][r][s]

// ---------------------------------------------------------------------------
__device__ __forceinline__ void ffma2(ull& d, ull a, ull b) {
    asm("fma.rn.f32x2 %0, %1, %2, %0;" : "+l"(d) : "l"(a), "l"(b));
}
__device__ __forceinline__ void ldgsts16(void* dst, const void* src) {
    unsigned saddr = (unsigned)__cvta_generic_to_shared(dst);
    asm volatile("cp.async.cg.shared.global [%0], [%1], 16;\n" :: "r"(saddr), "l"(src));
}
__device__ __forceinline__ void cp_commit() {
    asm volatile("cp.async.commit_group;\n" ::: "memory");
}
template <int N>
__device__ __forceinline__ void cp_wait() {
    asm volatile("cp.async.wait_group %0;\n" :: "n"(N) : "memory");
}

// ---------------------------------------------------------------------------
// K01 fused, 256 threads/block:
//   blocks [0,1024): WeffQ for 4 e-values each (+beff at block 0)
//   blocks [1024,1032): per-batch argmax + bucketed stream compaction
// ---------------------------------------------------------------------------
__global__ __launch_bounds__(256) void k01(const float* __restrict__ W1,
                                           const float* __restrict__ W2,
                                           const float* __restrict__ b1,
                                           const float* __restrict__ b2,
                                           const int* __restrict__ value,
                                           const int* __restrict__ depth) {
    int bid = blockIdx.x;
    int tid = threadIdx.x;

    if (bid < 1024) {
        // ---- Weff: 4 e-values per block ----
        __shared__ __align__(16) float w2s[512];
        __shared__ __align__(16) float w1r[4][512];
        int e0 = bid * 4;
        if (tid < 128) ((float4*)w2s)[tid] = ((const float4*)W2)[tid];
        ((float4*)&w1r[0][0])[tid]       = ((const float4*)(W1 + (size_t)e0 * 512))[tid];
        ((float4*)&w1r[0][0])[tid + 256] = ((const float4*)(W1 + (size_t)e0 * 512))[tid + 256];
        __syncthreads();
        int sub = tid >> 6;       // which e (0..3)
        int t64 = tid & 63;
        int s0 = t64 >> 3, s = t64 & 7;
        int e = e0 + sub;
        float acc = 0.f;
#pragma unroll
        for (int c = 0; c < 64; c++) acc += w1r[sub][c * 8 + s0] * w2s[c * 8 + s];
        int p = (e >> 1) & 1, h = e & 1;
        g_WeffQ[(s0 * 1024 + bid) * 32 + p * 16 + s * 2 + h] = acc;
        if (bid == 0 && tid < 8) {
            float a = 0.f;
#pragma unroll
            for (int c = 0; c < 64; c++) a += b1[c] * w2s[c * 8 + tid];
            g_beff[tid] = a + b2[0];
        }
    } else {
        // ---- prep: batch n, 256 threads, 64 elems/thread, no global atomics ----
        int n = bid - 1024;
        const int* dep = depth + n * TD;
        const int* val = value + n * TD;
        __shared__ int s_idx;
        __shared__ int wsum[8];
        __shared__ ull wtA[8], wtB[8];
        __shared__ int wbase[8 * 8];
        __shared__ int s_tot;

        int maxv = dep[TD - 1];
        if (tid == 0) { s_idx = TD; s_tot = 0; }
        __syncthreads();
        for (int t = tid; t < TD; t += 256) {
            if (dep[t] == maxv && (t == 0 || dep[t - 1] < maxv)) atomicMin(&s_idx, t);
        }
        __syncthreads();
        int idx = s_idx;

        int base = tid * 64;
        unsigned mb0 = 0, mb1 = 0;
        int cnt = 0;
        ull cA = 0, cB = 0;   // per-s0 counts: s0 0-3 in cA, 4-7 in cB, 16-bit fields
#pragma unroll
        for (int j = 0; j < 64; j++) {
            int t = base + j;
            bool m = (t < idx) && (val[t] == 2);
            if (j < 32) mb0 |= ((unsigned)m) << j;
            else        mb1 |= ((unsigned)m) << (j - 32);
            cnt += (int)m;
            if (m) {
                int f = j & 7;
                if (f < 4) cA += 1ull << (f * 16);
                else       cB += 1ull << ((f - 4) * 16);
            }
        }
        int lane = tid & 31, wid = tid >> 5;  // 8 warps
        int v = cnt;
        ull ciA = cA, ciB = cB;
#pragma unroll
        for (int o = 1; o < 32; o <<= 1) {
            int u   = __shfl_up_sync(0xffffffffu, v, o);
            ull uA  = __shfl_up_sync(0xffffffffu, ciA, o);
            ull uB  = __shfl_up_sync(0xffffffffu, ciB, o);
            if (lane >= o) { v += u; ciA += uA; ciB += uB; }
        }
        if (lane == 31) { wsum[wid] = v; wtA[wid] = ciA; wtB[wid] = ciB; }
        __syncthreads();
        if (tid == 0) {
            int run = 0;
#pragma unroll
            for (int w = 0; w < 8; w++) { int t = wsum[w]; wsum[w] = run; run += t; }
        } else if (tid >= 8 && tid < 16) {
            int s0 = tid - 8;
            int run = 0;
#pragma unroll
            for (int w = 0; w < 8; w++) {
                int c = (s0 < 4) ? (int)((wtA[w] >> (s0 * 16)) & 0xFFFF)
                                 : (int)((wtB[w] >> ((s0 - 4) * 16)) & 0xFFFF);
                wbase[w * 8 + s0] = run;
                run += c;
            }
            g_bcount[n * 8 + s0] = run;
            atomicAdd(&s_tot, run);
        }
        __syncthreads();
        int r = wsum[wid] + v - cnt;
        ull exA = ciA - cA, exB = ciB - cB;
        int slot[8];
#pragma unroll
        for (int s0 = 0; s0 < 8; s0++) {
            int ex = (s0 < 4) ? (int)((exA >> (s0 * 16)) & 0xFFFF)
                              : (int)((exB >> ((s0 - 4) * 16)) & 0xFFFF);
            slot[s0] = wbase[wid * 8 + s0] + ex;
        }
        int bb = n * 8;
#pragma unroll
        for (int j = 0; j < 64; j++) {
            bool m = (j < 32) ? ((mb0 >> j) & 1u) : ((mb1 >> (j - 32)) & 1u);
            if (m) {
                int t = base + j;
                int s0 = j & 7;
                g_bucket[(bb + s0) * 2048 + slot[s0]] = (r << 16) | (t >> 3);
                slot[s0]++;
                r++;
            }
        }
        if (tid == 0) g_count8[n] = 8 * s_tot;
    }
}

// ---------------------------------------------------------------------------
// K3: bucketed GEMM. 128 threads/block, 256 rows/block, thread owns 2 rows
// (tid, tid+128) x all 8 s. X staged via cp.async into smem with 20-float row
// stride (conflict-free), W warp-broadcast, f32x2 FMA. K split by ks into
// 512-float chunks; 32 double-buffered stages of KT=16.
// blockIdx.x = rb*64 + ks*8 + s0 (s0 fastest for L2 reuse across buckets).
// ---------------------------------------------------------------------------
#define XSTRIDE 20

__global__ __launch_bounds__(128) void k3_heavy(const float* __restrict__ x) {
    int bx = blockIdx.x;
    int s0 = bx & 7, ks = (bx >> 3) & 7, rb = bx >> 6;
    int n = blockIdx.y;
    int bucket = n * 8 + s0;
    int bcnt = g_bcount[bucket];
    int row0 = rb * MROWS;
    if (row0 >= bcnt) return;
    int tid = threadIdx.x;

    __shared__ __align__(16) float Xs[2][MROWS][XSTRIDE];  // 40KB
    __shared__ __align__(16) float Wsm[2][4][32];          // 1KB
    __shared__ int stp_s[MROWS];
    __shared__ int sr_s[MROWS];

    // prologue: row metadata (coalesced)
#pragma unroll
    for (int i = 0; i < 2; i++) {
        int li = tid + 128 * i;
        int gr = row0 + li;
        if (gr < bcnt) {
            int p = g_bucket[bucket * 2048 + gr];
            sr_s[li] = p >> 16;
            stp_s[li] = p & 0xFFFF;
        } else {
            sr_s[li] = -1;
            stp_s[li] = 0;
        }
    }
    __syncthreads();

    const float* xb = x + (size_t)n * TPD * ED + ks * KCHUNK;
    const float* wb = g_WeffQ + (size_t)(s0 * 1024 + ks * 128) * 32;

    // loader mapping: gidx = i*128+tid; row = gidx>>2, q = gidx&3
    auto load_stage = [&](int st, int b) {
        int kbase = st * KT;
#pragma unroll
        for (int i = 0; i < 8; i++) {
            int gidx = i * 128 + tid;
            int row = gidx >> 2, q = gidx & 3;
            ldgsts16(&Xs[b][row][q * 4],
                     xb + (size_t)stp_s[row] * ED + kbase + q * 4);
        }
        if (tid < 32) {
            ldgsts16(&Wsm[b][0][tid * 4], wb + st * 128 + tid * 4);
        }
        cp_commit();
    };

    load_stage(0, 0);

    ull acc[2][8];
#pragma unroll
    for (int i = 0; i < 2; i++)
#pragma unroll
        for (int s = 0; s < 8; s++) acc[i][s] = 0ull;

    for (int st = 0; st < NSTAGE; st++) {
        int b = st & 1;
        if (st + 1 < NSTAGE) {
            load_stage(st + 1, b ^ 1);
            cp_wait<1>();
        } else {
            cp_wait<0>();
        }
        __syncthreads();

#pragma unroll
        for (int q = 0; q < 4; q++) {
            ulonglong2 xq[2];
#pragma unroll
            for (int i = 0; i < 2; i++)
                xq[i] = *(const ulonglong2*)&Xs[b][tid + 128 * i][q * 4];
            const ull* wq = (const ull*)&Wsm[b][q][0];
#pragma unroll
            for (int sp = 0; sp < 4; sp++) {
                ulonglong2 w0 = *(const ulonglong2*)(wq + sp * 2);      // p=0
                ulonglong2 w1 = *(const ulonglong2*)(wq + 8 + sp * 2);  // p=1
#pragma unroll
                for (int i = 0; i < 2; i++) {
                    ffma2(acc[i][2 * sp],     xq[i].x, w0.x);
                    ffma2(acc[i][2 * sp],     xq[i].y, w1.x);
                    ffma2(acc[i][2 * sp + 1], xq[i].x, w0.y);
                    ffma2(acc[i][2 * sp + 1], xq[i].y, w1.y);
                }
            }
        }
        __syncthreads();
    }

    // store partials
#pragma unroll
    for (int i = 0; i < 2; i++) {
        int li = tid + 128 * i;
        int rr = sr_s[li];
        if (rr < 0) continue;
        float y[8];
#pragma unroll
        for (int s = 0; s < 8; s++) {
            float2 f = *(float2*)&acc[i][s];
            y[s] = f.x + f.y;
        }
        float* dst = g_part + ((size_t)(ks * NB + n) * RMAX + rr) * 8;
        *(float4*)(dst)     = make_float4(y[0], y[1], y[2], y[3]);
        *(float4*)(dst + 4) = make_float4(y[4], y[5], y[6], y[7]);
    }
}

// ---------------------------------------------------------------------------
// K4: fused epilogue + default fill. Strip of 256 output rows per block.
// ---------------------------------------------------------------------------
__global__ __launch_bounds__(256) void k4_epi(const float* __restrict__ W3,
                                              const float* __restrict__ b2,
                                              float* __restrict__ out) {
    int n = blockIdx.y;
    int j0 = blockIdx.x * 256;
    int tid = threadIdx.x;
    __shared__ float y2s[256];
    __shared__ float w3s[VD];
    __shared__ float beffs[8];
    if (tid < VD) w3s[tid] = W3[tid];
    if (tid < 8) beffs[tid] = g_beff[tid];
    __syncthreads();

    int count8 = g_count8[n];
    int j = j0 + tid;
    float acc;
    if (j < count8) {
        acc = beffs[j & 7];
#pragma unroll
        for (int ksi = 0; ksi < KS; ksi++)
            acc += g_part[(size_t)(ksi * NB + n) * (RMAX * 8) + j];
    } else {
        acc = b2[0];
    }
    y2s[tid] = acc;
    __syncthreads();

    float* ob = out + ((size_t)n * OUTROWS + j0) * VD;
    const int NF4 = 256 * VD / 4;  // 1088
    for (int f = tid; f < NF4; f += 256) {
        float4 o;
#pragma unroll
        for (int c = 0; c < 4; c++) {
            int idx = f * 4 + c;
            int jj = idx / VD;
            int vv = idx - jj * VD;
            ((float*)&o)[c] = y2s[jj] * w3s[vv];
        }
        *(float4*)(ob + f * 4) = o;
    }
}

// ---------------------------------------------------------------------------
extern "C" void kernel_launch(void* const* d_in, const int* in_sizes, int n_in,
                              void* d_out, int out_size) {
    const float* x     = (const float*)d_in[0];
    const int*   value = (const int*)d_in[1];   // jax x64-off: int32
    const int*   depth = (const int*)d_in[2];
    // d_in[3] = pos, unused
    const float* W1    = (const float*)d_in[4];
    const float* b1    = (const float*)d_in[5];
    const float* W2    = (const float*)d_in[6];
    const float* b2    = (const float*)d_in[7];
    const float* W3    = (const float*)d_in[8];
    float* out = (float*)d_out;

    k01<<<1032, 256>>>(W1, W2, b1, b2, value, depth);
    k3_heavy<<<dim3(512, NB), 128>>>(x);
    k4_epi<<<dim3(OUTROWS / 256, NB), 256>>>(W3, b2, out);
}